// round 7
// baseline (speedup 1.0000x reference)
#include <cuda_runtime.h>
#include <cuda_bf16.h>
#include <cstdint>
#include <math.h>

// ---------------------------------------------------------------- constants
#define BB   2
#define SS   2048
#define HIDD 2048
#define NH   32
#define NKV  8
#define DH   64
#define MROWS (BB*SS)        // 4096
#define KVDIM (NKV*DH)       // 512
#define KDIM  2048
#define K3   (3*KDIM)        // 6144 expanded-K
#define QKVDIM (HIDD + 2*KVDIM)   // 3072 merged output width

typedef unsigned long long u64t;

// ---------------------------------------------------------------- scratch
__device__ float g_qkv[(size_t)MROWS * QKVDIM];   // 48 MB (q | k | v per row)
__device__ float g_at [(size_t)MROWS * HIDD];     // 32 MB

__device__ __nv_bfloat16 g_hs_e[(size_t)MROWS * K3];    // 48 MB
__device__ __nv_bfloat16 g_w_e [(size_t)QKVDIM * K3];   // 36 MB (Wq|Wk|Wv rows)
__device__ __nv_bfloat16 g_wo_e[(size_t)HIDD  * K3];    // 24 MB
__device__ __nv_bfloat16 g_at_e[(size_t)MROWS * K3];    // 48 MB

// ---------------------------------------------------------------- helpers
__device__ __forceinline__ uint32_t smem_u32(const void* p) {
    uint32_t a;
    asm("{ .reg .u64 t; cvta.to.shared.u64 t, %1; cvt.u32.u64 %0, t; }" : "=r"(a) : "l"(p));
    return a;
}
__device__ __forceinline__ void cpa16(uint32_t s, const void* g) {
    asm volatile("cp.async.cg.shared.global [%0], [%1], 16;" :: "r"(s), "l"(g));
}
__device__ __forceinline__ void cpa_commit() {
    asm volatile("cp.async.commit_group;" ::: "memory");
}
template<int N> __device__ __forceinline__ void cpa_wait() {
    asm volatile("cp.async.wait_group %0;" :: "n"(N) : "memory");
}
__device__ __forceinline__ void ldsm_x4(uint32_t& r0, uint32_t& r1, uint32_t& r2, uint32_t& r3,
                                        uint32_t addr) {
    asm volatile("ldmatrix.sync.aligned.m8n8.x4.shared.b16 {%0,%1,%2,%3}, [%4];"
                 : "=r"(r0), "=r"(r1), "=r"(r2), "=r"(r3) : "r"(addr));
}
__device__ __forceinline__ void mma_bf16(float& c0, float& c1, float& c2, float& c3,
                                         uint32_t a0, uint32_t a1, uint32_t a2, uint32_t a3,
                                         uint32_t b0, uint32_t b1) {
    asm volatile(
        "mma.sync.aligned.m16n8k16.row.col.f32.bf16.bf16.f32 "
        "{%0,%1,%2,%3}, {%4,%5,%6,%7}, {%8,%9}, {%0,%1,%2,%3};"
        : "+f"(c0), "+f"(c1), "+f"(c2), "+f"(c3)
        : "r"(a0), "r"(a1), "r"(a2), "r"(a3), "r"(b0), "r"(b1));
}
// f32x2
__device__ __forceinline__ u64t pack2(float lo, float hi) {
    u64t d; asm("mov.b64 %0, {%1, %2};" : "=l"(d) : "f"(lo), "f"(hi)); return d;
}
__device__ __forceinline__ u64t pack_dup(float x) {
    u64t d; asm("mov.b64 %0, {%1, %1};" : "=l"(d) : "f"(x)); return d;
}
__device__ __forceinline__ void unpack2(u64t v, float& lo, float& hi) {
    asm("mov.b64 {%0, %1}, %2;" : "=f"(lo), "=f"(hi) : "l"(v));
}
__device__ __forceinline__ u64t fma2(u64t a, u64t b, u64t c) {
    u64t d; asm("fma.rn.f32x2 %0, %1, %2, %3;" : "=l"(d) : "l"(a), "l"(b), "l"(c)); return d;
}
__device__ __forceinline__ u64t mul2(u64t a, u64t b) {
    u64t d; asm("mul.rn.f32x2 %0, %1, %2;" : "=l"(d) : "l"(a), "l"(b)); return d;
}

// ---------------------------------------------------------------- split-expand
// A' = [hi | hi | lo], B' = [hi | lo | hi] so sum = hh + hl + lh (drop ll).
__global__ void expandA_kernel(const float* __restrict__ s, __nv_bfloat16* __restrict__ d, int M) {
    int idx = blockIdx.x * blockDim.x + threadIdx.x;
    if (idx >= M * KDIM) return;
    int m = idx / KDIM, k = idx - m * KDIM;
    float x = s[idx];
    __nv_bfloat16 hi = __float2bfloat16(x);
    __nv_bfloat16 lo = __float2bfloat16(x - __bfloat162float(hi));
    __nv_bfloat16* row = d + (size_t)m * K3;
    row[k] = hi; row[KDIM + k] = hi; row[2 * KDIM + k] = lo;
}
__global__ void expandB_kernel(const float* __restrict__ s, __nv_bfloat16* __restrict__ d, int M) {
    int idx = blockIdx.x * blockDim.x + threadIdx.x;
    if (idx >= M * KDIM) return;
    int m = idx / KDIM, k = idx - m * KDIM;
    float x = s[idx];
    __nv_bfloat16 hi = __float2bfloat16(x);
    __nv_bfloat16 lo = __float2bfloat16(x - __bfloat162float(hi));
    __nv_bfloat16* row = d + (size_t)m * K3;
    row[k] = hi; row[KDIM + k] = lo; row[2 * KDIM + k] = hi;
}

// ---------------------------------------------------------------- bf16 HMMA GEMM
// C[M,N] = A'[M,K3] * B'[N,K3]^T. 128x128 CTA tile, BK=64, 2-stage, occ 2.
#define BK    64
#define NKIT  (K3 / BK)          // 96
#define SROWB 144                // 128B data + 16B pad
#define TILE_B (128 * SROWB)     // 18432
#define STAGE_B (2 * TILE_B)     // A + B = 36864
#define GSMEM  (2 * STAGE_B)     // 73728

__global__ __launch_bounds__(256, 2) void gemm_bf16(
    const __nv_bfloat16* __restrict__ A, const __nv_bfloat16* __restrict__ B,
    float* __restrict__ C, int N)
{
    extern __shared__ __align__(128) char smem[];
    const uint32_t sb = smem_u32(smem);
    const int tid  = threadIdx.x;
    const int lane = tid & 31;
    const int wid  = tid >> 5;
    const int wm   = wid & 3;
    const int wn   = wid >> 2;
    const int bm = blockIdx.y * 128, bn = blockIdx.x * 128;

    // loader: threads 0-127 -> A rows, 128-255 -> B rows; one 128B row each
    const int lr = tid & 127;
    const bool isB = tid >= 128;
    const __nv_bfloat16* gsrc = isB ? B + (size_t)(bn + lr) * K3
                                    : A + (size_t)(bm + lr) * K3;
    const uint32_t sdst = sb + (isB ? TILE_B : 0) + lr * SROWB;

    float acc[2][8][4];
#pragma unroll
    for (int i = 0; i < 2; i++)
#pragma unroll
        for (int j = 0; j < 8; j++)
#pragma unroll
            for (int r = 0; r < 4; r++) acc[i][j][r] = 0.f;

    const int a_row = wm * 32 + (lane & 15);
    const int a_kb  = (lane >> 4) * 16;
    const int b_row = wn * 64 + ((lane >> 4) << 3) + (lane & 7);
    const int b_kb  = ((lane >> 3) & 1) * 16;

    // prologue: stage 0
#pragma unroll
    for (int c = 0; c < 8; c++) cpa16(sdst + c * 16, gsrc + c * 8);
    cpa_commit();

    for (int kt = 0; kt < NKIT; kt++) {
        cpa_wait<0>();
        __syncthreads();

        if (kt + 1 < NKIT) {
            const uint32_t sd = sdst + ((kt + 1) & 1) * STAGE_B;
            const int k0 = (kt + 1) * BK;
#pragma unroll
            for (int c = 0; c < 8; c++) cpa16(sd + c * 16, gsrc + k0 + c * 8);
            cpa_commit();
        }

        const uint32_t sA = sb + (kt & 1) * STAGE_B;
        const uint32_t sB = sA + TILE_B;

#pragma unroll
        for (int kh = 0; kh < 4; kh++) {          // four k16 steps per BK=64
            const int kbyte = kh * 32;
            uint32_t a[2][4];
#pragma unroll
            for (int mt = 0; mt < 2; mt++)
                ldsm_x4(a[mt][0], a[mt][1], a[mt][2], a[mt][3],
                        sA + (a_row + mt * 16) * SROWB + kbyte + a_kb);
            uint32_t b[4][4];
#pragma unroll
            for (int nt = 0; nt < 4; nt++)
                ldsm_x4(b[nt][0], b[nt][1], b[nt][2], b[nt][3],
                        sB + (b_row + nt * 16) * SROWB + kbyte + b_kb);
#pragma unroll
            for (int mt = 0; mt < 2; mt++)
#pragma unroll
                for (int j = 0; j < 8; j++)
                    mma_bf16(acc[mt][j][0], acc[mt][j][1], acc[mt][j][2], acc[mt][j][3],
                             a[mt][0], a[mt][1], a[mt][2], a[mt][3],
                             b[j >> 1][(j & 1) * 2], b[j >> 1][(j & 1) * 2 + 1]);
        }
        __syncthreads();
    }

#pragma unroll
    for (int mt = 0; mt < 2; mt++) {
        int m0 = bm + wm * 32 + mt * 16 + (lane >> 2);
#pragma unroll
        for (int j = 0; j < 8; j++) {
            int n0 = bn + wn * 64 + j * 8 + (lane & 3) * 2;
            float2 v0 = { acc[mt][j][0], acc[mt][j][1] };
            float2 v1 = { acc[mt][j][2], acc[mt][j][3] };
            *(float2*)(C + (size_t)m0 * N + n0)       = v0;
            *(float2*)(C + (size_t)(m0 + 8) * N + n0) = v1;
        }
    }
}

// ---------------------------------------------------------------- RoPE (on merged qkv)
__global__ void rope_kernel(float* __restrict__ qkv,
                            const float* __restrict__ cs, const float* __restrict__ sn)
{
    const int QP = MROWS * NH  * (DH / 2);
    const int KP = MROWS * NKV * (DH / 2);
    int idx = blockIdx.x * blockDim.x + threadIdx.x;
    if (idx < QP) {
        int d = idx & 31;
        int h = (idx >> 5) & (NH - 1);
        int r = idx >> 10;
        float c = cs[r * DH + d], s = sn[r * DH + d];
        float* p = qkv + (size_t)r * QKVDIM + h * DH + d;
        float x1 = p[0], x2 = p[32];
        p[0]  = x1 * c - x2 * s;
        p[32] = x2 * c + x1 * s;
    } else if (idx < QP + KP) {
        int j = idx - QP;
        int d = j & 31;
        int h = (j >> 5) & (NKV - 1);
        int r = j >> 8;
        float c = cs[r * DH + d], s = sn[r * DH + d];
        float* p = qkv + (size_t)r * QKVDIM + HIDD + h * DH + d;
        float x1 = p[0], x2 = p[32];
        p[0]  = x1 * c - x2 * s;
        p[32] = x2 * c + x1 * s;
    }
}

// ---------------------------------------------------------------- attention (f32x2)
#define AQ 128
#define AK 32
#define KPAD 68

__global__ __launch_bounds__(128) void attn_kernel(
    const float* __restrict__ QKV, float* __restrict__ O)
{
    __shared__ float Ks[AK][KPAD];
    __shared__ float Vs[AK][KPAD];

    const int tid = threadIdx.x;
    const int b   = blockIdx.y >> 5;
    const int h   = blockIdx.y & 31;
    const int kvh = h >> 2;
    const int qrow = blockIdx.x * AQ + tid;

    const float scale = 0.125f;
    const float* qp = QKV + (size_t)(b * SS + qrow) * QKVDIM + h * DH;

    u64t q2[DH / 2], o2[DH / 2];
#pragma unroll
    for (int i = 0; i < DH / 4; i++) {
        float4 v = *(const float4*)(qp + 4 * i);
        q2[2 * i + 0] = pack2(v.x * scale, v.y * scale);
        q2[2 * i + 1] = pack2(v.z * scale, v.w * scale);
        o2[2 * i + 0] = pack2(0.f, 0.f);
        o2[2 * i + 1] = pack2(0.f, 0.f);
    }

    float m = -1e30f, l = 0.f;
    const int nt = (blockIdx.x * AQ + AQ) / AK;

    const int lj   = tid >> 2;
    const int loff = (tid & 3) << 2;

    for (int t = 0; t < nt; t++) {
        const int k0 = t * AK;
        __syncthreads();
        {
            const float* kp = QKV + (size_t)(b * SS + k0 + lj) * QKVDIM + HIDD + kvh * DH;
            const float* vp = kp + KVDIM;
#pragma unroll
            for (int i = 0; i < 4; i++) {
                int c = loff + 16 * i;
                *(float4*)&Ks[lj][c] = *(const float4*)(kp + c);
                *(float4*)&Vs[lj][c] = *(const float4*)(vp + c);
            }
        }
        __syncthreads();

        float s[AK];
        float tmax = -1e30f;
#pragma unroll
        for (int j = 0; j < AK; j++) {
            u64t acc = pack2(0.f, 0.f);
#pragma unroll
            for (int d = 0; d < DH / 4; d++) {
                ulonglong2 kk2 = *(const ulonglong2*)&Ks[j][4 * d];
                acc = fma2(q2[2 * d + 0], kk2.x, acc);
                acc = fma2(q2[2 * d + 1], kk2.y, acc);
            }
            float alo, ahi;
            unpack2(acc, alo, ahi);
            float sc = alo + ahi;
            sc = (k0 + j <= qrow) ? sc : -1e30f;
            s[j] = sc;
            tmax = fmaxf(tmax, sc);
        }

        if (tmax > m) {
            float mn = tmax;
            float corr = __expf(m - mn);
            m = mn;
            l *= corr;
            u64t cd = pack_dup(corr);
#pragma unroll
            for (int d = 0; d < DH / 2; d++) o2[d] = mul2(o2[d], cd);
        }

#pragma unroll
        for (int j = 0; j < AK; j++) {
            float p = __expf(s[j] - m);
            l += p;
            u64t pd = pack_dup(p);
#pragma unroll
            for (int d = 0; d < DH / 4; d++) {
                ulonglong2 v2 = *(const ulonglong2*)&Vs[j][4 * d];
                o2[2 * d + 0] = fma2(pd, v2.x, o2[2 * d + 0]);
                o2[2 * d + 1] = fma2(pd, v2.y, o2[2 * d + 1]);
            }
        }
    }

    const float inv = 1.f / l;
    float* op = O + (size_t)(b * SS + qrow) * HIDD + h * DH;
#pragma unroll
    for (int d = 0; d < DH / 4; d++) {
        float x0, x1, x2, x3;
        unpack2(o2[2 * d + 0], x0, x1);
        unpack2(o2[2 * d + 1], x2, x3);
        float4 v = { x0 * inv, x1 * inv, x2 * inv, x3 * inv };
        *(float4*)(op + 4 * d) = v;
    }
}

// ---------------------------------------------------------------- launch
extern "C" void kernel_launch(void* const* d_in, const int* in_sizes, int n_in,
                              void* d_out, int out_size)
{
    const float* hs = (const float*)d_in[0];
    const float* cs = (const float*)d_in[1];
    const float* sn = (const float*)d_in[2];
    const float* Wq = (const float*)d_in[4];
    const float* Wk = (const float*)d_in[5];
    const float* Wv = (const float*)d_in[6];
    const float* Wo = (const float*)d_in[7];
    float* out = (float*)d_out;

    float *qkv, *at;
    cudaGetSymbolAddress((void**)&qkv, g_qkv);
    cudaGetSymbolAddress((void**)&at,  g_at);
    __nv_bfloat16 *hse, *we, *woe, *ate;
    cudaGetSymbolAddress((void**)&hse, g_hs_e);
    cudaGetSymbolAddress((void**)&we,  g_w_e);
    cudaGetSymbolAddress((void**)&woe, g_wo_e);
    cudaGetSymbolAddress((void**)&ate, g_at_e);

    cudaFuncSetAttribute(gemm_bf16, cudaFuncAttributeMaxDynamicSharedMemorySize, GSMEM);

    const int nHS = MROWS * KDIM, nWQ = HIDD * KDIM, nWK = KVDIM * KDIM;
    expandA_kernel<<<(nHS + 255) / 256, 256>>>(hs, hse, MROWS);
    expandB_kernel<<<(nWQ + 255) / 256, 256>>>(Wq, we, HIDD);
    expandB_kernel<<<(nWK + 255) / 256, 256>>>(Wk, we + (size_t)HIDD * K3, KVDIM);
    expandB_kernel<<<(nWK + 255) / 256, 256>>>(Wv, we + (size_t)(HIDD + KVDIM) * K3, KVDIM);
    expandB_kernel<<<(nWQ + 255) / 256, 256>>>(Wo, woe, HIDD);

    // merged QKV projection: [4096, 6144] x [3072, 6144]^T -> g_qkv
    gemm_bf16<<<dim3(QKVDIM / 128, MROWS / 128), 256, GSMEM>>>(hse, we, qkv, QKVDIM);

    const int pairs = MROWS * NH * (DH / 2) + MROWS * NKV * (DH / 2);
    rope_kernel<<<pairs / 256, 256>>>(qkv, cs, sn);

    attn_kernel<<<dim3(SS / AQ, BB * NH), dim3(128)>>>(qkv, at);

    expandA_kernel<<<(nHS + 255) / 256, 256>>>(at, ate, MROWS);
    gemm_bf16<<<dim3(HIDD / 128, MROWS / 128), 256, GSMEM>>>(ate, woe, out, HIDD);
}

// round 8
// speedup vs baseline: 1.7820x; 1.7820x over previous
#include <cuda_runtime.h>
#include <cuda_bf16.h>
#include <cstdint>
#include <math.h>

// ---------------------------------------------------------------- constants
#define BB   2
#define SS   2048
#define HIDD 2048
#define NH   32
#define NKV  8
#define DH   64
#define MROWS (BB*SS)        // 4096
#define KVDIM (NKV*DH)       // 512
#define KDIM  2048
#define K3   (3*KDIM)        // 6144 expanded-K
#define QKVDIM (HIDD + 2*KVDIM)   // 3072 merged output width

typedef unsigned long long u64t;

// ---------------------------------------------------------------- scratch
__device__ float g_qkv[(size_t)MROWS * QKVDIM];   // 48 MB (q | k | v per row)
__device__ float g_at [(size_t)MROWS * HIDD];     // 32 MB

__device__ __nv_bfloat16 g_hs_e[(size_t)MROWS * K3];    // 48 MB
__device__ __nv_bfloat16 g_w_e [(size_t)QKVDIM * K3];   // 36 MB (Wq|Wk|Wv rows)
__device__ __nv_bfloat16 g_wo_e[(size_t)HIDD  * K3];    // 24 MB
__device__ __nv_bfloat16 g_at_e[(size_t)MROWS * K3];    // 48 MB

// ---------------------------------------------------------------- helpers
__device__ __forceinline__ uint32_t smem_u32(const void* p) {
    uint32_t a;
    asm("{ .reg .u64 t; cvta.to.shared.u64 t, %1; cvt.u32.u64 %0, t; }" : "=r"(a) : "l"(p));
    return a;
}
__device__ __forceinline__ void cpa16(uint32_t s, const void* g) {
    asm volatile("cp.async.cg.shared.global [%0], [%1], 16;" :: "r"(s), "l"(g));
}
__device__ __forceinline__ void cpa_commit() {
    asm volatile("cp.async.commit_group;" ::: "memory");
}
template<int N> __device__ __forceinline__ void cpa_wait() {
    asm volatile("cp.async.wait_group %0;" :: "n"(N) : "memory");
}
__device__ __forceinline__ void ldsm_x4(uint32_t& r0, uint32_t& r1, uint32_t& r2, uint32_t& r3,
                                        uint32_t addr) {
    asm volatile("ldmatrix.sync.aligned.m8n8.x4.shared.b16 {%0,%1,%2,%3}, [%4];"
                 : "=r"(r0), "=r"(r1), "=r"(r2), "=r"(r3) : "r"(addr));
}
__device__ __forceinline__ void mma_bf16(float& c0, float& c1, float& c2, float& c3,
                                         uint32_t a0, uint32_t a1, uint32_t a2, uint32_t a3,
                                         uint32_t b0, uint32_t b1) {
    asm volatile(
        "mma.sync.aligned.m16n8k16.row.col.f32.bf16.bf16.f32 "
        "{%0,%1,%2,%3}, {%4,%5,%6,%7}, {%8,%9}, {%0,%1,%2,%3};"
        : "+f"(c0), "+f"(c1), "+f"(c2), "+f"(c3)
        : "r"(a0), "r"(a1), "r"(a2), "r"(a3), "r"(b0), "r"(b1));
}
// f32x2
__device__ __forceinline__ u64t pack2(float lo, float hi) {
    u64t d; asm("mov.b64 %0, {%1, %2};" : "=l"(d) : "f"(lo), "f"(hi)); return d;
}
__device__ __forceinline__ u64t pack_dup(float x) {
    u64t d; asm("mov.b64 %0, {%1, %1};" : "=l"(d) : "f"(x)); return d;
}
__device__ __forceinline__ void unpack2(u64t v, float& lo, float& hi) {
    asm("mov.b64 {%0, %1}, %2;" : "=f"(lo), "=f"(hi) : "l"(v));
}
__device__ __forceinline__ u64t fma2(u64t a, u64t b, u64t c) {
    u64t d; asm("fma.rn.f32x2 %0, %1, %2, %3;" : "=l"(d) : "l"(a), "l"(b), "l"(c)); return d;
}
__device__ __forceinline__ u64t mul2(u64t a, u64t b) {
    u64t d; asm("mul.rn.f32x2 %0, %1, %2;" : "=l"(d) : "l"(a), "l"(b)); return d;
}

// ---------------------------------------------------------------- split-expand
// A' = [hi | hi | lo], B' = [hi | lo | hi] so sum = hh + hl + lh (drop ll).
__global__ void expandA_kernel(const float* __restrict__ s, __nv_bfloat16* __restrict__ d, int M) {
    int idx = blockIdx.x * blockDim.x + threadIdx.x;
    if (idx >= M * KDIM) return;
    int m = idx / KDIM, k = idx - m * KDIM;
    float x = s[idx];
    __nv_bfloat16 hi = __float2bfloat16(x);
    __nv_bfloat16 lo = __float2bfloat16(x - __bfloat162float(hi));
    __nv_bfloat16* row = d + (size_t)m * K3;
    row[k] = hi; row[KDIM + k] = hi; row[2 * KDIM + k] = lo;
}
__global__ void expandB_kernel(const float* __restrict__ s, __nv_bfloat16* __restrict__ d, int M) {
    int idx = blockIdx.x * blockDim.x + threadIdx.x;
    if (idx >= M * KDIM) return;
    int m = idx / KDIM, k = idx - m * KDIM;
    float x = s[idx];
    __nv_bfloat16 hi = __float2bfloat16(x);
    __nv_bfloat16 lo = __float2bfloat16(x - __bfloat162float(hi));
    __nv_bfloat16* row = d + (size_t)m * K3;
    row[k] = hi; row[KDIM + k] = lo; row[2 * KDIM + k] = hi;
}

// ---------------------------------------------------------------- bf16 HMMA GEMM (R3/R6 exact)
#define BK3   32
#define NK3   (K3 / BK3)         // 192
#define SROWB 80
#define ATILE_B (128 * SROWB)
#define STAGE_B (2 * ATILE_B)
#define GSMEM  (3 * STAGE_B)

__global__ __launch_bounds__(256) void gemm_bf16(
    const __nv_bfloat16* __restrict__ A, const __nv_bfloat16* __restrict__ B,
    float* __restrict__ C, int N)
{
    extern __shared__ __align__(128) char smem[];
    const uint32_t sb = smem_u32(smem);
    const int tid  = threadIdx.x;
    const int lane = tid & 31;
    const int wid  = tid >> 5;
    const int wm   = wid & 3;
    const int wn   = wid >> 2;
    const int bm = blockIdx.y * 128, bn = blockIdx.x * 128;

    const int lrow = tid >> 1;
    const int lc   = (tid & 1) * 2;
    const __nv_bfloat16* Ab = A + (size_t)(bm + lrow) * K3 + lc * 8;
    const __nv_bfloat16* Bb = B + (size_t)(bn + lrow) * K3 + lc * 8;
    const uint32_t saA = sb + lrow * SROWB + lc * 16;
    const uint32_t saB = sb + ATILE_B + lrow * SROWB + lc * 16;

    float acc[2][8][4];
#pragma unroll
    for (int i = 0; i < 2; i++)
#pragma unroll
        for (int j = 0; j < 8; j++)
#pragma unroll
            for (int r = 0; r < 4; r++) acc[i][j][r] = 0.f;

    const int a_row = wm * 32 + (lane & 15);
    const int a_kb  = (lane >> 4) * 16;
    const int b_row = wn * 64 + ((lane >> 4) << 3) + (lane & 7);
    const int b_kb  = ((lane >> 3) & 1) * 16;

#pragma unroll
    for (int s = 0; s < 2; s++) {
        cpa16(saA + s * STAGE_B,      Ab + s * BK3);
        cpa16(saA + s * STAGE_B + 16, Ab + s * BK3 + 8);
        cpa16(saB + s * STAGE_B,      Bb + s * BK3);
        cpa16(saB + s * STAGE_B + 16, Bb + s * BK3 + 8);
        cpa_commit();
    }

    for (int kt = 0; kt < NK3; kt++) {
        cpa_wait<1>();
        __syncthreads();

        if (kt + 2 < NK3) {
            const int ps = (kt + 2) % 3;
            cpa16(saA + ps * STAGE_B,      Ab + (kt + 2) * BK3);
            cpa16(saA + ps * STAGE_B + 16, Ab + (kt + 2) * BK3 + 8);
            cpa16(saB + ps * STAGE_B,      Bb + (kt + 2) * BK3);
            cpa16(saB + ps * STAGE_B + 16, Bb + (kt + 2) * BK3 + 8);
        }
        cpa_commit();

        const uint32_t sAs = sb + (kt % 3) * STAGE_B;
        const uint32_t sBs = sAs + ATILE_B;

#pragma unroll
        for (int kh = 0; kh < 2; kh++) {
            const int kbyte = kh * 32;
            uint32_t a[2][4];
#pragma unroll
            for (int mt = 0; mt < 2; mt++)
                ldsm_x4(a[mt][0], a[mt][1], a[mt][2], a[mt][3],
                        sAs + (a_row + mt * 16) * SROWB + kbyte + a_kb);
            uint32_t b[4][4];
#pragma unroll
            for (int nt = 0; nt < 4; nt++)
                ldsm_x4(b[nt][0], b[nt][1], b[nt][2], b[nt][3],
                        sBs + (b_row + nt * 16) * SROWB + kbyte + b_kb);
#pragma unroll
            for (int mt = 0; mt < 2; mt++)
#pragma unroll
                for (int j = 0; j < 8; j++)
                    mma_bf16(acc[mt][j][0], acc[mt][j][1], acc[mt][j][2], acc[mt][j][3],
                             a[mt][0], a[mt][1], a[mt][2], a[mt][3],
                             b[j >> 1][(j & 1) * 2], b[j >> 1][(j & 1) * 2 + 1]);
        }
        __syncthreads();
    }

#pragma unroll
    for (int mt = 0; mt < 2; mt++) {
        int m0 = bm + wm * 32 + mt * 16 + (lane >> 2);
#pragma unroll
        for (int j = 0; j < 8; j++) {
            int n0 = bn + wn * 64 + j * 8 + (lane & 3) * 2;
            float2 v0 = { acc[mt][j][0], acc[mt][j][1] };
            float2 v1 = { acc[mt][j][2], acc[mt][j][3] };
            *(float2*)(C + (size_t)m0 * N + n0)       = v0;
            *(float2*)(C + (size_t)(m0 + 8) * N + n0) = v1;
        }
    }
}

// ---------------------------------------------------------------- RoPE (merged qkv strides)
__global__ void rope_kernel(float* __restrict__ qkv,
                            const float* __restrict__ cs, const float* __restrict__ sn)
{
    const int QP = MROWS * NH  * (DH / 2);
    const int KP = MROWS * NKV * (DH / 2);
    int idx = blockIdx.x * blockDim.x + threadIdx.x;
    if (idx < QP) {
        int d = idx & 31;
        int h = (idx >> 5) & (NH - 1);
        int r = idx >> 10;
        float c = cs[r * DH + d], s = sn[r * DH + d];
        float* p = qkv + (size_t)r * QKVDIM + h * DH + d;
        float x1 = p[0], x2 = p[32];
        p[0]  = x1 * c - x2 * s;
        p[32] = x2 * c + x1 * s;
    } else if (idx < QP + KP) {
        int j = idx - QP;
        int d = j & 31;
        int h = (j >> 5) & (NKV - 1);
        int r = j >> 8;
        float c = cs[r * DH + d], s = sn[r * DH + d];
        float* p = qkv + (size_t)r * QKVDIM + HIDD + h * DH + d;
        float x1 = p[0], x2 = p[32];
        p[0]  = x1 * c - x2 * s;
        p[32] = x2 * c + x1 * s;
    }
}

// ---------------------------------------------------------------- attention (f32x2, R6)
#define AQ 128
#define AK 32
#define KPAD 68

__global__ __launch_bounds__(128) void attn_kernel(
    const float* __restrict__ QKV, float* __restrict__ O)
{
    __shared__ float Ks[AK][KPAD];
    __shared__ float Vs[AK][KPAD];

    const int tid = threadIdx.x;
    const int b   = blockIdx.y >> 5;
    const int h   = blockIdx.y & 31;
    const int kvh = h >> 2;
    const int qrow = blockIdx.x * AQ + tid;

    const float scale = 0.125f;
    const float* qp = QKV + (size_t)(b * SS + qrow) * QKVDIM + h * DH;

    u64t q2[DH / 2], o2[DH / 2];
#pragma unroll
    for (int i = 0; i < DH / 4; i++) {
        float4 v = *(const float4*)(qp + 4 * i);
        q2[2 * i + 0] = pack2(v.x * scale, v.y * scale);
        q2[2 * i + 1] = pack2(v.z * scale, v.w * scale);
        o2[2 * i + 0] = pack2(0.f, 0.f);
        o2[2 * i + 1] = pack2(0.f, 0.f);
    }

    float m = -1e30f, l = 0.f;
    const int nt = (blockIdx.x * AQ + AQ) / AK;

    const int lj   = tid >> 2;
    const int loff = (tid & 3) << 2;

    for (int t = 0; t < nt; t++) {
        const int k0 = t * AK;
        __syncthreads();
        {
            const float* kp = QKV + (size_t)(b * SS + k0 + lj) * QKVDIM + HIDD + kvh * DH;
            const float* vp = kp + KVDIM;
#pragma unroll
            for (int i = 0; i < 4; i++) {
                int c = loff + 16 * i;
                *(float4*)&Ks[lj][c] = *(const float4*)(kp + c);
                *(float4*)&Vs[lj][c] = *(const float4*)(vp + c);
            }
        }
        __syncthreads();

        float s[AK];
        float tmax = -1e30f;
#pragma unroll
        for (int j = 0; j < AK; j++) {
            u64t acc = pack2(0.f, 0.f);
#pragma unroll
            for (int d = 0; d < DH / 4; d++) {
                ulonglong2 kk2 = *(const ulonglong2*)&Ks[j][4 * d];
                acc = fma2(q2[2 * d + 0], kk2.x, acc);
                acc = fma2(q2[2 * d + 1], kk2.y, acc);
            }
            float alo, ahi;
            unpack2(acc, alo, ahi);
            float sc = alo + ahi;
            sc = (k0 + j <= qrow) ? sc : -1e30f;
            s[j] = sc;
            tmax = fmaxf(tmax, sc);
        }

        if (tmax > m) {
            float mn = tmax;
            float corr = __expf(m - mn);
            m = mn;
            l *= corr;
            u64t cd = pack_dup(corr);
#pragma unroll
            for (int d = 0; d < DH / 2; d++) o2[d] = mul2(o2[d], cd);
        }

#pragma unroll
        for (int j = 0; j < AK; j++) {
            float p = __expf(s[j] - m);
            l += p;
            u64t pd = pack_dup(p);
#pragma unroll
            for (int d = 0; d < DH / 4; d++) {
                ulonglong2 v2 = *(const ulonglong2*)&Vs[j][4 * d];
                o2[2 * d + 0] = fma2(pd, v2.x, o2[2 * d + 0]);
                o2[2 * d + 1] = fma2(pd, v2.y, o2[2 * d + 1]);
            }
        }
    }

    const float inv = 1.f / l;
    float* op = O + (size_t)(b * SS + qrow) * HIDD + h * DH;
#pragma unroll
    for (int d = 0; d < DH / 4; d++) {
        float x0, x1, x2, x3;
        unpack2(o2[2 * d + 0], x0, x1);
        unpack2(o2[2 * d + 1], x2, x3);
        float4 v = { x0 * inv, x1 * inv, x2 * inv, x3 * inv };
        *(float4*)(op + 4 * d) = v;
    }
}

// ---------------------------------------------------------------- launch
extern "C" void kernel_launch(void* const* d_in, const int* in_sizes, int n_in,
                              void* d_out, int out_size)
{
    const float* hs = (const float*)d_in[0];
    const float* cs = (const float*)d_in[1];
    const float* sn = (const float*)d_in[2];
    const float* Wq = (const float*)d_in[4];
    const float* Wk = (const float*)d_in[5];
    const float* Wv = (const float*)d_in[6];
    const float* Wo = (const float*)d_in[7];
    float* out = (float*)d_out;

    float *qkv, *at;
    cudaGetSymbolAddress((void**)&qkv, g_qkv);
    cudaGetSymbolAddress((void**)&at,  g_at);
    __nv_bfloat16 *hse, *we, *woe, *ate;
    cudaGetSymbolAddress((void**)&hse, g_hs_e);
    cudaGetSymbolAddress((void**)&we,  g_w_e);
    cudaGetSymbolAddress((void**)&woe, g_wo_e);
    cudaGetSymbolAddress((void**)&ate, g_at_e);

    cudaFuncSetAttribute(gemm_bf16, cudaFuncAttributeMaxDynamicSharedMemorySize, GSMEM);

    const int nHS = MROWS * KDIM, nWQ = HIDD * KDIM, nWK = KVDIM * KDIM;
    expandA_kernel<<<(nHS + 255) / 256, 256>>>(hs, hse, MROWS);
    expandB_kernel<<<(nWQ + 255) / 256, 256>>>(Wq, we, HIDD);
    expandB_kernel<<<(nWK + 255) / 256, 256>>>(Wk, we + (size_t)HIDD * K3, KVDIM);
    expandB_kernel<<<(nWK + 255) / 256, 256>>>(Wv, we + (size_t)(HIDD + KVDIM) * K3, KVDIM);
    expandB_kernel<<<(nWQ + 255) / 256, 256>>>(Wo, woe, HIDD);

    // merged QKV projection: [4096, 6144] x [3072, 6144]^T -> g_qkv
    gemm_bf16<<<dim3(QKVDIM / 128, MROWS / 128), 256, GSMEM>>>(hse, we, qkv, QKVDIM);

    const int pairs = MROWS * NH * (DH / 2) + MROWS * NKV * (DH / 2);
    rope_kernel<<<pairs / 256, 256>>>(qkv, cs, sn);

    attn_kernel<<<dim3(SS / AQ, BB * NH), dim3(128)>>>(qkv, at);

    expandA_kernel<<<(nHS + 255) / 256, 256>>>(at, ate, MROWS);
    gemm_bf16<<<dim3(HIDD / 128, MROWS / 128), 256, GSMEM>>>(ate, woe, out, HIDD);
}